// round 13
// baseline (speedup 1.0000x reference)
#include <cuda_runtime.h>
#include <cuda_fp16.h>
#include <cstdint>
#include <cstddef>

// Problem constants
#define T_SEQ 2048
#define DM    1024
#define C3    3072
#define NH    16
#define HD    64
#define KK    1024

// ---------------------------------------------------------------------------
// Scratch (device globals: allocation-free per harness rules)
// ---------------------------------------------------------------------------
__device__ __half g_xh[(size_t)4096 * 1024];    // x fp16
__device__ __half g_qkvh[(size_t)4096 * 3072];  // qkv fp16 [B*T, 3C]
__device__ __half g_atth[(size_t)4096 * 1024];  // attn out fp16
__device__ __half g_wqh[(size_t)3072 * 1024];   // w_qkv^T fp16 [N,K]
__device__ __half g_wph[(size_t)1024 * 1024];   // w_proj^T fp16 [N,K]

// ---------------------------------------------------------------------------
// mma.sync / ldmatrix / cp.async helpers (plain sm_103-compatible PTX)
// ---------------------------------------------------------------------------
__device__ __forceinline__ uint32_t cvta_s(const void* p) {
    return (uint32_t)__cvta_generic_to_shared(p);
}
__device__ __forceinline__ void cp_async16(uint32_t saddr, const void* g) {
    asm volatile("cp.async.cg.shared.global [%0], [%1], 16;"
                 :: "r"(saddr), "l"(g) : "memory");
}
__device__ __forceinline__ void ldmx4(uint32_t* r, uint32_t addr) {
    asm volatile("ldmatrix.sync.aligned.m8n8.x4.shared.b16 {%0,%1,%2,%3}, [%4];"
                 : "=r"(r[0]), "=r"(r[1]), "=r"(r[2]), "=r"(r[3]) : "r"(addr));
}
__device__ __forceinline__ void ldmx4_trans(uint32_t* r, uint32_t addr) {
    asm volatile("ldmatrix.sync.aligned.m8n8.x4.trans.shared.b16 {%0,%1,%2,%3}, [%4];"
                 : "=r"(r[0]), "=r"(r[1]), "=r"(r[2]), "=r"(r[3]) : "r"(addr));
}
__device__ __forceinline__ void mma_f16(float* c, const uint32_t* a,
                                        uint32_t b0, uint32_t b1) {
    asm volatile(
        "mma.sync.aligned.m16n8k16.row.col.f32.f16.f16.f32 "
        "{%0,%1,%2,%3}, {%4,%5,%6,%7}, {%8,%9}, {%0,%1,%2,%3};"
        : "+f"(c[0]), "+f"(c[1]), "+f"(c[2]), "+f"(c[3])
        : "r"(a[0]), "r"(a[1]), "r"(a[2]), "r"(a[3]), "r"(b0), "r"(b1));
}
__device__ __forceinline__ uint32_t pack_h2(float a, float b) {
    __half2 h = __floats2half2_rn(a, b);
    return *(uint32_t*)&h;
}

// ---------------------------------------------------------------------------
// Conversion kernels
// ---------------------------------------------------------------------------
__global__ __launch_bounds__(256) void convh_kernel(
    const float* __restrict__ in, __half* __restrict__ out)
{
    int i = blockIdx.x * 256 + threadIdx.x;
    float4 v = ((const float4*)in)[i];
    ((__half2*)out)[2 * i + 0] = __floats2half2_rn(v.x, v.y);
    ((__half2*)out)[2 * i + 1] = __floats2half2_rn(v.z, v.w);
}

// w [1024, N] fp32 -> wT [N, 1024] fp16 (transpose + convert)
__global__ __launch_bounds__(256) void tconvh_kernel(
    const float* __restrict__ w, __half* __restrict__ out, int N)
{
    __shared__ float t[32][33];
    const int n0 = blockIdx.x << 5;
    const int k0 = blockIdx.y << 5;
    const int tx = threadIdx.x & 31;
    const int ty = threadIdx.x >> 5;
#pragma unroll
    for (int i = 0; i < 4; i++)
        t[ty + 8 * i][tx] = w[(size_t)(k0 + ty + 8 * i) * N + n0 + tx];
    __syncthreads();
#pragma unroll
    for (int i = 0; i < 4; i++) {
        int r = ty + 8 * i;
        out[(size_t)(n0 + r) * KK + k0 + tx] = __float2half(t[tx][r]);
    }
}

// ---------------------------------------------------------------------------
// fp16 tensor-core GEMM: C[M,N] = A[M,1024] @ B[N,1024]^T + bias
// 128x128 tile, BK=32, 3-stage cp.async pipeline, one sync per K-iter.
// ---------------------------------------------------------------------------
#define ASTR 40

template <bool HALF_OUT>
__global__ __launch_bounds__(256) void gemm_mma_kernel(
    const __half* __restrict__ A, const __half* __restrict__ B,
    const float* __restrict__ bias, float* __restrict__ Cf,
    __half* __restrict__ Ch, int M, int N)
{
    extern __shared__ __half dsm[];
    __half* Asm = dsm;
    __half* Bsm = dsm + 3 * 128 * ASTR;

    const int tid  = threadIdx.x;
    const int lane = tid & 31;
    const int wid  = tid >> 5;
    const int wm   = wid & 3;
    const int wn   = wid >> 2;
    const int m0   = (int)blockIdx.y << 7;
    const int n0   = (int)blockIdx.x << 7;

    float acc[2][8][4];
#pragma unroll
    for (int i = 0; i < 2; i++)
#pragma unroll
        for (int j = 0; j < 8; j++)
#pragma unroll
            for (int k = 0; k < 4; k++) acc[i][j][k] = 0.f;

    const __half* Ag = A + (size_t)m0 * KK;
    const __half* Bg = B + (size_t)n0 * KK;

    const int r0 = tid >> 2;
    const int c0 = (tid & 3) << 3;

    auto stage_load = [&](int s, int kb) {
        __half* As = Asm + s * 128 * ASTR;
        __half* Bs = Bsm + s * 128 * ASTR;
#pragma unroll
        for (int j = 0; j < 2; j++) {
            int r = r0 + (j << 6);
            cp_async16(cvta_s(As + r * ASTR + c0), Ag + (size_t)r * KK + kb + c0);
            cp_async16(cvta_s(Bs + r * ASTR + c0), Bg + (size_t)r * KK + kb + c0);
        }
        asm volatile("cp.async.commit_group;" ::: "memory");
    };

    const int nk = KK >> 5;   // 32
    stage_load(0, 0);
    stage_load(1, 32);

    const int arow  = wm * 32 + (lane & 15);
    const int acsel = (lane >> 4) << 3;
    const int brow  = wn * 64 + (lane & 7) + ((lane >> 4) << 3);
    const int bksel = ((lane >> 3) & 1) << 3;

    for (int kt = 0; kt < nk; kt++) {
        if (kt + 1 < nk) asm volatile("cp.async.wait_group 1;" ::: "memory");
        else             asm volatile("cp.async.wait_group 0;" ::: "memory");
        __syncthreads();
        if (kt + 2 < nk) stage_load((kt + 2) % 3, (kt + 2) << 5);

        const __half* As = Asm + (kt % 3) * 128 * ASTR;
        const __half* Bs = Bsm + (kt % 3) * 128 * ASTR;
#pragma unroll
        for (int ks = 0; ks < 32; ks += 16) {
            uint32_t af[2][4];
#pragma unroll
            for (int am = 0; am < 2; am++)
                ldmx4(af[am], cvta_s(As + (arow + am * 16) * ASTR + ks + acsel));
#pragma unroll
            for (int bn = 0; bn < 4; bn++) {
                uint32_t bf[4];
                ldmx4(bf, cvta_s(Bs + (brow + bn * 16) * ASTR + ks + bksel));
#pragma unroll
                for (int am = 0; am < 2; am++) {
                    mma_f16(acc[am][2 * bn],     af[am], bf[0], bf[1]);
                    mma_f16(acc[am][2 * bn + 1], af[am], bf[2], bf[3]);
                }
            }
        }
    }

    const int trow = lane >> 2;
    const int tcol = (lane & 3) << 1;
#pragma unroll
    for (int am = 0; am < 2; am++) {
#pragma unroll
        for (int bn = 0; bn < 8; bn++) {
            int col = n0 + wn * 64 + bn * 8 + tcol;
            float2 bv = *(const float2*)(bias + col);
            int rg = m0 + wm * 32 + am * 16 + trow;
            float x0 = acc[am][bn][0] + bv.x, y0 = acc[am][bn][1] + bv.y;
            float x1 = acc[am][bn][2] + bv.x, y1 = acc[am][bn][3] + bv.y;
            if (HALF_OUT) {
                *(__half2*)(Ch + (size_t)rg * N + col)       = __floats2half2_rn(x0, y0);
                *(__half2*)(Ch + (size_t)(rg + 8) * N + col) = __floats2half2_rn(x1, y1);
            } else {
                float2 o0 = {x0, y0}, o1 = {x1, y1};
                *(float2*)(Cf + (size_t)rg * N + col)       = o0;
                *(float2*)(Cf + (size_t)(rg + 8) * N + col) = o1;
            }
        }
    }
}

// ---------------------------------------------------------------------------
// Tensor-core flash attention, fp16 in/out, fp32 accumulate.
// CTA = 128 queries of one (b,h); 8 warps x 16 rows; key blocks of 64.
// 3-stage cp.async KV pipeline (load kb+2 issued BEFORE compute kb).
// Q pre-scaled by 0.125*log2(e); softmax via exp2f; diagonal-only masking.
// ---------------------------------------------------------------------------
#define QSTR 72
#define KVSTG 18432   // bytes per KV stage (K 64x72 + V 64x72 halves)

__global__ __launch_bounds__(256, 3) void attn_mma_kernel(
    const __half* __restrict__ qkv, __half* __restrict__ outa)
{
    extern __shared__ char dsma[];
    __half (*Qs)[QSTR] = (__half(*)[QSTR])dsma;
    char* kvb = dsma + 128 * QSTR * 2;   // 18432

    const int tid  = threadIdx.x;
    const int lane = tid & 31;
    const int wid  = tid >> 5;
    const int bh = blockIdx.x;
    const int b  = bh >> 4;
    const int h  = bh & 15;
    const int m0 = (int)(gridDim.y - 1 - blockIdx.y) << 7;  // longest first
    const int qrow0 = wid << 4;

    // Load Q tile, pre-scaled by 0.125*log2(e)
    const __half2 hscl = __float2half2_rn(0.125f * 1.4426950408889634f);
    const __half* qb = qkv + ((size_t)(b * T_SEQ + m0)) * C3 + h * HD;
    for (int i = tid; i < 1024; i += 256) {
        int r = i >> 3, c = (i & 7) << 3;
        uint4 v = *(const uint4*)(qb + (size_t)r * C3 + c);
        __half2* d = (__half2*)&Qs[r][c];
        d[0] = __hmul2(((__half2*)&v)[0], hscl);
        d[1] = __hmul2(((__half2*)&v)[1], hscl);
        d[2] = __hmul2(((__half2*)&v)[2], hscl);
        d[3] = __hmul2(((__half2*)&v)[3], hscl);
    }

    auto load_stage = [&](int s, int n0) {
        const __half* kp = qkv + ((size_t)(b * T_SEQ + n0)) * C3 + DM + h * HD;
        const __half* vp = kp + DM;
        char* base = kvb + s * KVSTG;
        for (int i = tid; i < 1024; i += 256) {
            int isV = i >> 9;
            int j = i & 511;
            int r = j >> 3, c = (j & 7) << 3;
            const __half* src = (isV ? vp : kp) + (size_t)r * C3 + c;
            cp_async16(cvta_s(base + isV * 9216 + r * (QSTR * 2) + c * 2), src);
        }
        asm volatile("cp.async.commit_group;" ::: "memory");
    };

    float m_[2] = {-1e30f, -1e30f};
    float l_[2] = {0.f, 0.f};
    float o[8][4];
#pragma unroll
    for (int j = 0; j < 8; j++)
#pragma unroll
        for (int k = 0; k < 4; k++) o[j][k] = 0.f;

    const int rA = m0 + qrow0 + (lane >> 2);
    const int rB = rA + 8;

    const int nkb = (m0 >> 6) + 2;
    load_stage(0, 0);
    load_stage(1, 64);

    for (int kb = 0; kb < nkb; kb++) {
        if (kb + 1 < nkb) asm volatile("cp.async.wait_group 1;" ::: "memory");
        else              asm volatile("cp.async.wait_group 0;" ::: "memory");
        __syncthreads();
        if (kb + 2 < nkb) load_stage((kb + 2) % 3, (kb + 2) << 6);

        const int n0 = kb << 6;
        char* stg = kvb + (kb % 3) * KVSTG;
        __half (*Ks)[QSTR] = (__half(*)[QSTR])stg;
        __half (*Vs)[QSTR] = (__half(*)[QSTR])(stg + 9216);

        if (m0 + qrow0 + 15 < n0) continue;   // fully masked warp tile

        // S = Q @ K^T  (Q pre-scaled)
        float s_[8][4];
#pragma unroll
        for (int j = 0; j < 8; j++)
#pragma unroll
            for (int k = 0; k < 4; k++) s_[j][k] = 0.f;

#pragma unroll
        for (int ks = 0; ks < 64; ks += 16) {
            uint32_t a[4];
            ldmx4(a, cvta_s(&Qs[qrow0 + (lane & 15)][ks + ((lane >> 4) << 3)]));
#pragma unroll
            for (int j = 0; j < 4; j++) {
                uint32_t bf[4];
                ldmx4(bf, cvta_s(&Ks[j * 16 + (lane & 7) + ((lane >> 4) << 3)]
                                    [ks + (((lane >> 3) & 1) << 3)]));
                mma_f16(s_[2 * j],     a, bf[0], bf[1]);
                mma_f16(s_[2 * j + 1], a, bf[2], bf[3]);
            }
        }

        // causal mask only when this warp tile straddles the diagonal
        if (n0 + 63 > m0 + qrow0) {
#pragma unroll
            for (int j = 0; j < 8; j++) {
                int cg = n0 + j * 8 + ((lane & 3) << 1);
                if (cg     > rA) s_[j][0] = -1e30f;
                if (cg + 1 > rA) s_[j][1] = -1e30f;
                if (cg     > rB) s_[j][2] = -1e30f;
                if (cg + 1 > rB) s_[j][3] = -1e30f;
            }
        }

        // online softmax (base-2 domain), quad-lane reduction
        float mxA = -1e30f, mxB = -1e30f;
#pragma unroll
        for (int j = 0; j < 8; j++) {
            mxA = fmaxf(mxA, fmaxf(s_[j][0], s_[j][1]));
            mxB = fmaxf(mxB, fmaxf(s_[j][2], s_[j][3]));
        }
        mxA = fmaxf(mxA, __shfl_xor_sync(0xffffffffu, mxA, 1));
        mxA = fmaxf(mxA, __shfl_xor_sync(0xffffffffu, mxA, 2));
        mxB = fmaxf(mxB, __shfl_xor_sync(0xffffffffu, mxB, 1));
        mxB = fmaxf(mxB, __shfl_xor_sync(0xffffffffu, mxB, 2));

        float mnA = fmaxf(m_[0], mxA), mnB = fmaxf(m_[1], mxB);
        float cA = exp2f(m_[0] - mnA), cB = exp2f(m_[1] - mnB);
        m_[0] = mnA; m_[1] = mnB;

        float sumA = 0.f, sumB = 0.f;
#pragma unroll
        for (int j = 0; j < 8; j++) {
            s_[j][0] = exp2f(s_[j][0] - mnA);
            s_[j][1] = exp2f(s_[j][1] - mnA);
            s_[j][2] = exp2f(s_[j][2] - mnB);
            s_[j][3] = exp2f(s_[j][3] - mnB);
            sumA += s_[j][0] + s_[j][1];
            sumB += s_[j][2] + s_[j][3];
        }
        sumA += __shfl_xor_sync(0xffffffffu, sumA, 1);
        sumA += __shfl_xor_sync(0xffffffffu, sumA, 2);
        sumB += __shfl_xor_sync(0xffffffffu, sumB, 1);
        sumB += __shfl_xor_sync(0xffffffffu, sumB, 2);
        l_[0] = l_[0] * cA + sumA;
        l_[1] = l_[1] * cB + sumB;

#pragma unroll
        for (int j = 0; j < 8; j++) {
            o[j][0] *= cA; o[j][1] *= cA;
            o[j][2] *= cB; o[j][3] *= cB;
        }

        // O += P @ V
#pragma unroll
        for (int t = 0; t < 4; t++) {
            uint32_t aP[4];
            aP[0] = pack_h2(s_[2 * t][0],     s_[2 * t][1]);
            aP[1] = pack_h2(s_[2 * t][2],     s_[2 * t][3]);
            aP[2] = pack_h2(s_[2 * t + 1][0], s_[2 * t + 1][1]);
            aP[3] = pack_h2(s_[2 * t + 1][2], s_[2 * t + 1][3]);
#pragma unroll
            for (int jd = 0; jd < 4; jd++) {
                uint32_t bf[4];
                ldmx4_trans(bf, cvta_s(&Vs[t * 16 + (((lane >> 3) & 1) << 3) + (lane & 7)]
                                          [jd * 16 + ((lane >> 4) << 3)]));
                mma_f16(o[2 * jd],     aP, bf[0], bf[1]);
                mma_f16(o[2 * jd + 1], aP, bf[2], bf[3]);
            }
        }
    }

    // epilogue: normalize, write fp16 [B*T, 1024] at head offset
    float invA = 1.f / l_[0], invB = 1.f / l_[1];
    __half* oA = outa + ((size_t)(b * T_SEQ) + rA) * DM + h * HD;
    __half* oB = outa + ((size_t)(b * T_SEQ) + rB) * DM + h * HD;
#pragma unroll
    for (int j = 0; j < 8; j++) {
        int col = j * 8 + ((lane & 3) << 1);
        *(__half2*)(oA + col) = __floats2half2_rn(o[j][0] * invA, o[j][1] * invA);
        *(__half2*)(oB + col) = __floats2half2_rn(o[j][2] * invB, o[j][3] * invB);
    }
}

// ---------------------------------------------------------------------------
extern "C" void kernel_launch(void* const* d_in, const int* in_sizes, int n_in,
                              void* d_out, int out_size)
{
    const float* x      = (const float*)d_in[0];
    const float* w_qkv  = (const float*)d_in[1];
    const float* b_qkv  = (const float*)d_in[2];
    const float* w_proj = (const float*)d_in[3];
    const float* b_proj = (const float*)d_in[4];
    float* out = (float*)d_out;

    __half *xh, *qkvh, *atth, *wqh, *wph;
    cudaGetSymbolAddress((void**)&xh, g_xh);
    cudaGetSymbolAddress((void**)&qkvh, g_qkvh);
    cudaGetSymbolAddress((void**)&atth, g_atth);
    cudaGetSymbolAddress((void**)&wqh, g_wqh);
    cudaGetSymbolAddress((void**)&wph, g_wph);

    const int smem_gemm = 3 * 2 * 128 * ASTR * (int)sizeof(__half);  // 61440
    cudaFuncSetAttribute(gemm_mma_kernel<true>,
                         cudaFuncAttributeMaxDynamicSharedMemorySize, smem_gemm);
    cudaFuncSetAttribute(gemm_mma_kernel<false>,
                         cudaFuncAttributeMaxDynamicSharedMemorySize, smem_gemm);
    const int smem_attn = 128 * QSTR * 2 + 3 * KVSTG;  // 73728
    cudaFuncSetAttribute(attn_mma_kernel,
                         cudaFuncAttributeMaxDynamicSharedMemorySize, smem_attn);

    // 1) x -> fp16
    convh_kernel<<<4096, 256>>>(x, xh);
    // 2) w_qkv -> transposed fp16 [3072,1024]
    tconvh_kernel<<<dim3(96, 32), 256>>>(w_qkv, wqh, 3072);
    // 3) QKV GEMM (fp16 out, bias fused)
    gemm_mma_kernel<true><<<dim3(24, 32), 256, smem_gemm>>>(
        xh, wqh, b_qkv, nullptr, qkvh, 4096, 3072);
    // 4) causal flash attention (fp16 in/out)
    attn_mma_kernel<<<dim3(2 * NH, T_SEQ / 128), 256, smem_attn>>>(qkvh, atth);
    // 5) w_proj -> transposed fp16 [1024,1024]
    tconvh_kernel<<<dim3(32, 32), 256>>>(w_proj, wph, 1024);
    // 6) proj GEMM (fp32 out, bias fused)
    gemm_mma_kernel<false><<<dim3(8, 32), 256, smem_gemm>>>(
        atth, wph, b_proj, out, nullptr, 4096, 1024);
}

// round 15
// speedup vs baseline: 1.0638x; 1.0638x over previous
#include <cuda_runtime.h>
#include <cuda_fp16.h>
#include <cstdint>
#include <cstddef>

// Problem constants
#define T_SEQ 2048
#define DM    1024
#define C3    3072
#define NH    16
#define HD    64
#define KK    1024

// ---------------------------------------------------------------------------
// Scratch (device globals: allocation-free per harness rules)
// ---------------------------------------------------------------------------
__device__ __half g_xh[(size_t)4096 * 1024];    // x fp16
__device__ __half g_qkvh[(size_t)4096 * 3072];  // qkv fp16 [B*T, 3C]
__device__ __half g_atth[(size_t)4096 * 1024];  // attn out fp16
__device__ __half g_wqh[(size_t)3072 * 1024];   // w_qkv^T fp16 [N,K]
__device__ __half g_wph[(size_t)1024 * 1024];   // w_proj^T fp16 [N,K]

// ---------------------------------------------------------------------------
// mma.sync / ldmatrix / cp.async helpers (plain sm_103-compatible PTX)
// ---------------------------------------------------------------------------
__device__ __forceinline__ uint32_t cvta_s(const void* p) {
    return (uint32_t)__cvta_generic_to_shared(p);
}
__device__ __forceinline__ void cp_async16(uint32_t saddr, const void* g) {
    asm volatile("cp.async.cg.shared.global [%0], [%1], 16;"
                 :: "r"(saddr), "l"(g) : "memory");
}
__device__ __forceinline__ void ldmx4(uint32_t* r, uint32_t addr) {
    asm volatile("ldmatrix.sync.aligned.m8n8.x4.shared.b16 {%0,%1,%2,%3}, [%4];"
                 : "=r"(r[0]), "=r"(r[1]), "=r"(r[2]), "=r"(r[3]) : "r"(addr));
}
__device__ __forceinline__ void ldmx4_trans(uint32_t* r, uint32_t addr) {
    asm volatile("ldmatrix.sync.aligned.m8n8.x4.trans.shared.b16 {%0,%1,%2,%3}, [%4];"
                 : "=r"(r[0]), "=r"(r[1]), "=r"(r[2]), "=r"(r[3]) : "r"(addr));
}
__device__ __forceinline__ void mma_f16(float* c, const uint32_t* a,
                                        uint32_t b0, uint32_t b1) {
    asm volatile(
        "mma.sync.aligned.m16n8k16.row.col.f32.f16.f16.f32 "
        "{%0,%1,%2,%3}, {%4,%5,%6,%7}, {%8,%9}, {%0,%1,%2,%3};"
        : "+f"(c[0]), "+f"(c[1]), "+f"(c[2]), "+f"(c[3])
        : "r"(a[0]), "r"(a[1]), "r"(a[2]), "r"(a[3]), "r"(b0), "r"(b1));
}
__device__ __forceinline__ uint32_t pack_h2(float a, float b) {
    __half2 h = __floats2half2_rn(a, b);
    return *(uint32_t*)&h;
}

// ---------------------------------------------------------------------------
// Conversion kernels
// ---------------------------------------------------------------------------
__global__ __launch_bounds__(256) void convh_kernel(
    const float* __restrict__ in, __half* __restrict__ out)
{
    int i = blockIdx.x * 256 + threadIdx.x;
    float4 v = ((const float4*)in)[i];
    ((__half2*)out)[2 * i + 0] = __floats2half2_rn(v.x, v.y);
    ((__half2*)out)[2 * i + 1] = __floats2half2_rn(v.z, v.w);
}

// w [1024, N] fp32 -> wT [N, 1024] fp16 (transpose + convert)
__global__ __launch_bounds__(256) void tconvh_kernel(
    const float* __restrict__ w, __half* __restrict__ out, int N)
{
    __shared__ float t[32][33];
    const int n0 = blockIdx.x << 5;
    const int k0 = blockIdx.y << 5;
    const int tx = threadIdx.x & 31;
    const int ty = threadIdx.x >> 5;
#pragma unroll
    for (int i = 0; i < 4; i++)
        t[ty + 8 * i][tx] = w[(size_t)(k0 + ty + 8 * i) * N + n0 + tx];
    __syncthreads();
#pragma unroll
    for (int i = 0; i < 4; i++) {
        int r = ty + 8 * i;
        out[(size_t)(n0 + r) * KK + k0 + tx] = __float2half(t[tx][r]);
    }
}

// ---------------------------------------------------------------------------
// fp16 tensor-core GEMM: C[M,N] = A[M,1024] @ B[N,1024]^T + bias
// 128x128 tile, BK=32, 3-stage cp.async pipeline, one sync per K-iter.
// ---------------------------------------------------------------------------
#define ASTR 40

template <bool HALF_OUT>
__global__ __launch_bounds__(256) void gemm_mma_kernel(
    const __half* __restrict__ A, const __half* __restrict__ B,
    const float* __restrict__ bias, float* __restrict__ Cf,
    __half* __restrict__ Ch, int M, int N)
{
    extern __shared__ __half dsm[];
    __half* Asm = dsm;
    __half* Bsm = dsm + 3 * 128 * ASTR;

    const int tid  = threadIdx.x;
    const int lane = tid & 31;
    const int wid  = tid >> 5;
    const int wm   = wid & 3;
    const int wn   = wid >> 2;
    const int m0   = (int)blockIdx.y << 7;
    const int n0   = (int)blockIdx.x << 7;

    float acc[2][8][4];
#pragma unroll
    for (int i = 0; i < 2; i++)
#pragma unroll
        for (int j = 0; j < 8; j++)
#pragma unroll
            for (int k = 0; k < 4; k++) acc[i][j][k] = 0.f;

    const __half* Ag = A + (size_t)m0 * KK;
    const __half* Bg = B + (size_t)n0 * KK;

    const int r0 = tid >> 2;
    const int c0 = (tid & 3) << 3;

    auto stage_load = [&](int s, int kb) {
        __half* As = Asm + s * 128 * ASTR;
        __half* Bs = Bsm + s * 128 * ASTR;
#pragma unroll
        for (int j = 0; j < 2; j++) {
            int r = r0 + (j << 6);
            cp_async16(cvta_s(As + r * ASTR + c0), Ag + (size_t)r * KK + kb + c0);
            cp_async16(cvta_s(Bs + r * ASTR + c0), Bg + (size_t)r * KK + kb + c0);
        }
        asm volatile("cp.async.commit_group;" ::: "memory");
    };

    const int nk = KK >> 5;   // 32
    stage_load(0, 0);
    stage_load(1, 32);

    const int arow  = wm * 32 + (lane & 15);
    const int acsel = (lane >> 4) << 3;
    const int brow  = wn * 64 + (lane & 7) + ((lane >> 4) << 3);
    const int bksel = ((lane >> 3) & 1) << 3;

    for (int kt = 0; kt < nk; kt++) {
        if (kt + 1 < nk) asm volatile("cp.async.wait_group 1;" ::: "memory");
        else             asm volatile("cp.async.wait_group 0;" ::: "memory");
        __syncthreads();
        if (kt + 2 < nk) stage_load((kt + 2) % 3, (kt + 2) << 5);

        const __half* As = Asm + (kt % 3) * 128 * ASTR;
        const __half* Bs = Bsm + (kt % 3) * 128 * ASTR;
#pragma unroll
        for (int ks = 0; ks < 32; ks += 16) {
            uint32_t af[2][4];
#pragma unroll
            for (int am = 0; am < 2; am++)
                ldmx4(af[am], cvta_s(As + (arow + am * 16) * ASTR + ks + acsel));
#pragma unroll
            for (int bn = 0; bn < 4; bn++) {
                uint32_t bf[4];
                ldmx4(bf, cvta_s(Bs + (brow + bn * 16) * ASTR + ks + bksel));
#pragma unroll
                for (int am = 0; am < 2; am++) {
                    mma_f16(acc[am][2 * bn],     af[am], bf[0], bf[1]);
                    mma_f16(acc[am][2 * bn + 1], af[am], bf[2], bf[3]);
                }
            }
        }
    }

    const int trow = lane >> 2;
    const int tcol = (lane & 3) << 1;
#pragma unroll
    for (int am = 0; am < 2; am++) {
#pragma unroll
        for (int bn = 0; bn < 8; bn++) {
            int col = n0 + wn * 64 + bn * 8 + tcol;
            float2 bv = *(const float2*)(bias + col);
            int rg = m0 + wm * 32 + am * 16 + trow;
            float x0 = acc[am][bn][0] + bv.x, y0 = acc[am][bn][1] + bv.y;
            float x1 = acc[am][bn][2] + bv.x, y1 = acc[am][bn][3] + bv.y;
            if (HALF_OUT) {
                *(__half2*)(Ch + (size_t)rg * N + col)       = __floats2half2_rn(x0, y0);
                *(__half2*)(Ch + (size_t)(rg + 8) * N + col) = __floats2half2_rn(x1, y1);
            } else {
                float2 o0 = {x0, y0}, o1 = {x1, y1};
                *(float2*)(Cf + (size_t)rg * N + col)       = o0;
                *(float2*)(Cf + (size_t)(rg + 8) * N + col) = o1;
            }
        }
    }
}

// ---------------------------------------------------------------------------
// Tensor-core flash attention, fp16 in/out, fp32 accumulate.
// CTA = 128 queries of one (b,h); 8 warps x 16 rows; key blocks of 64.
// 3-stage cp.async KV pipeline (load kb+2 issued BEFORE compute kb).
// Q pre-scaled by 0.125*log2(e); softmax via exp2f; diagonal-only masking.
// Natural register allocation (no occupancy clamp — lb(256,3) measured -12us).
// ---------------------------------------------------------------------------
#define QSTR 72
#define KVSTG 18432   // bytes per KV stage (K 64x72 + V 64x72 halves)

__global__ __launch_bounds__(256) void attn_mma_kernel(
    const __half* __restrict__ qkv, __half* __restrict__ outa)
{
    extern __shared__ char dsma[];
    __half (*Qs)[QSTR] = (__half(*)[QSTR])dsma;
    char* kvb = dsma + 128 * QSTR * 2;   // 18432

    const int tid  = threadIdx.x;
    const int lane = tid & 31;
    const int wid  = tid >> 5;
    const int bh = blockIdx.x;
    const int b  = bh >> 4;
    const int h  = bh & 15;
    const int m0 = (int)(gridDim.y - 1 - blockIdx.y) << 7;  // longest first
    const int qrow0 = wid << 4;

    // Load Q tile, pre-scaled by 0.125*log2(e)
    const __half2 hscl = __float2half2_rn(0.125f * 1.4426950408889634f);
    const __half* qb = qkv + ((size_t)(b * T_SEQ + m0)) * C3 + h * HD;
    for (int i = tid; i < 1024; i += 256) {
        int r = i >> 3, c = (i & 7) << 3;
        uint4 v = *(const uint4*)(qb + (size_t)r * C3 + c);
        __half2* d = (__half2*)&Qs[r][c];
        d[0] = __hmul2(((__half2*)&v)[0], hscl);
        d[1] = __hmul2(((__half2*)&v)[1], hscl);
        d[2] = __hmul2(((__half2*)&v)[2], hscl);
        d[3] = __hmul2(((__half2*)&v)[3], hscl);
    }

    auto load_stage = [&](int s, int n0) {
        const __half* kp = qkv + ((size_t)(b * T_SEQ + n0)) * C3 + DM + h * HD;
        const __half* vp = kp + DM;
        char* base = kvb + s * KVSTG;
        for (int i = tid; i < 1024; i += 256) {
            int isV = i >> 9;
            int j = i & 511;
            int r = j >> 3, c = (j & 7) << 3;
            const __half* src = (isV ? vp : kp) + (size_t)r * C3 + c;
            cp_async16(cvta_s(base + isV * 9216 + r * (QSTR * 2) + c * 2), src);
        }
        asm volatile("cp.async.commit_group;" ::: "memory");
    };

    float m_[2] = {-1e30f, -1e30f};
    float l_[2] = {0.f, 0.f};
    float o[8][4];
#pragma unroll
    for (int j = 0; j < 8; j++)
#pragma unroll
        for (int k = 0; k < 4; k++) o[j][k] = 0.f;

    const int rA = m0 + qrow0 + (lane >> 2);
    const int rB = rA + 8;

    const int nkb = (m0 >> 6) + 2;
    load_stage(0, 0);
    load_stage(1, 64);

    for (int kb = 0; kb < nkb; kb++) {
        if (kb + 1 < nkb) asm volatile("cp.async.wait_group 1;" ::: "memory");
        else              asm volatile("cp.async.wait_group 0;" ::: "memory");
        __syncthreads();
        if (kb + 2 < nkb) load_stage((kb + 2) % 3, (kb + 2) << 6);

        const int n0 = kb << 6;
        char* stg = kvb + (kb % 3) * KVSTG;
        __half (*Ks)[QSTR] = (__half(*)[QSTR])stg;
        __half (*Vs)[QSTR] = (__half(*)[QSTR])(stg + 9216);

        if (m0 + qrow0 + 15 < n0) continue;   // fully masked warp tile

        // S = Q @ K^T  (Q pre-scaled)
        float s_[8][4];
#pragma unroll
        for (int j = 0; j < 8; j++)
#pragma unroll
            for (int k = 0; k < 4; k++) s_[j][k] = 0.f;

#pragma unroll
        for (int ks = 0; ks < 64; ks += 16) {
            uint32_t a[4];
            ldmx4(a, cvta_s(&Qs[qrow0 + (lane & 15)][ks + ((lane >> 4) << 3)]));
#pragma unroll
            for (int j = 0; j < 4; j++) {
                uint32_t bf[4];
                ldmx4(bf, cvta_s(&Ks[j * 16 + (lane & 7) + ((lane >> 4) << 3)]
                                    [ks + (((lane >> 3) & 1) << 3)]));
                mma_f16(s_[2 * j],     a, bf[0], bf[1]);
                mma_f16(s_[2 * j + 1], a, bf[2], bf[3]);
            }
        }

        // causal mask only when this warp tile straddles the diagonal
        if (n0 + 63 > m0 + qrow0) {
#pragma unroll
            for (int j = 0; j < 8; j++) {
                int cg = n0 + j * 8 + ((lane & 3) << 1);
                if (cg     > rA) s_[j][0] = -1e30f;
                if (cg + 1 > rA) s_[j][1] = -1e30f;
                if (cg     > rB) s_[j][2] = -1e30f;
                if (cg + 1 > rB) s_[j][3] = -1e30f;
            }
        }

        // online softmax (base-2 domain), quad-lane reduction
        float mxA = -1e30f, mxB = -1e30f;
#pragma unroll
        for (int j = 0; j < 8; j++) {
            mxA = fmaxf(mxA, fmaxf(s_[j][0], s_[j][1]));
            mxB = fmaxf(mxB, fmaxf(s_[j][2], s_[j][3]));
        }
        mxA = fmaxf(mxA, __shfl_xor_sync(0xffffffffu, mxA, 1));
        mxA = fmaxf(mxA, __shfl_xor_sync(0xffffffffu, mxA, 2));
        mxB = fmaxf(mxB, __shfl_xor_sync(0xffffffffu, mxB, 1));
        mxB = fmaxf(mxB, __shfl_xor_sync(0xffffffffu, mxB, 2));

        float mnA = fmaxf(m_[0], mxA), mnB = fmaxf(m_[1], mxB);
        float cA = exp2f(m_[0] - mnA), cB = exp2f(m_[1] - mnB);
        m_[0] = mnA; m_[1] = mnB;

        float sumA = 0.f, sumB = 0.f;
#pragma unroll
        for (int j = 0; j < 8; j++) {
            s_[j][0] = exp2f(s_[j][0] - mnA);
            s_[j][1] = exp2f(s_[j][1] - mnA);
            s_[j][2] = exp2f(s_[j][2] - mnB);
            s_[j][3] = exp2f(s_[j][3] - mnB);
            sumA += s_[j][0] + s_[j][1];
            sumB += s_[j][2] + s_[j][3];
        }
        sumA += __shfl_xor_sync(0xffffffffu, sumA, 1);
        sumA += __shfl_xor_sync(0xffffffffu, sumA, 2);
        sumB += __shfl_xor_sync(0xffffffffu, sumB, 1);
        sumB += __shfl_xor_sync(0xffffffffu, sumB, 2);
        l_[0] = l_[0] * cA + sumA;
        l_[1] = l_[1] * cB + sumB;

#pragma unroll
        for (int j = 0; j < 8; j++) {
            o[j][0] *= cA; o[j][1] *= cA;
            o[j][2] *= cB; o[j][3] *= cB;
        }

        // O += P @ V
#pragma unroll
        for (int t = 0; t < 4; t++) {
            uint32_t aP[4];
            aP[0] = pack_h2(s_[2 * t][0],     s_[2 * t][1]);
            aP[1] = pack_h2(s_[2 * t][2],     s_[2 * t][3]);
            aP[2] = pack_h2(s_[2 * t + 1][0], s_[2 * t + 1][1]);
            aP[3] = pack_h2(s_[2 * t + 1][2], s_[2 * t + 1][3]);
#pragma unroll
            for (int jd = 0; jd < 4; jd++) {
                uint32_t bf[4];
                ldmx4_trans(bf, cvta_s(&Vs[t * 16 + (((lane >> 3) & 1) << 3) + (lane & 7)]
                                          [jd * 16 + ((lane >> 4) << 3)]));
                mma_f16(o[2 * jd],     aP, bf[0], bf[1]);
                mma_f16(o[2 * jd + 1], aP, bf[2], bf[3]);
            }
        }
    }

    // epilogue: normalize, write fp16 [B*T, 1024] at head offset
    float invA = 1.f / l_[0], invB = 1.f / l_[1];
    __half* oA = outa + ((size_t)(b * T_SEQ) + rA) * DM + h * HD;
    __half* oB = outa + ((size_t)(b * T_SEQ) + rB) * DM + h * HD;
#pragma unroll
    for (int j = 0; j < 8; j++) {
        int col = j * 8 + ((lane & 3) << 1);
        *(__half2*)(oA + col) = __floats2half2_rn(o[j][0] * invA, o[j][1] * invA);
        *(__half2*)(oB + col) = __floats2half2_rn(o[j][2] * invB, o[j][3] * invB);
    }
}

// ---------------------------------------------------------------------------
extern "C" void kernel_launch(void* const* d_in, const int* in_sizes, int n_in,
                              void* d_out, int out_size)
{
    const float* x      = (const float*)d_in[0];
    const float* w_qkv  = (const float*)d_in[1];
    const float* b_qkv  = (const float*)d_in[2];
    const float* w_proj = (const float*)d_in[3];
    const float* b_proj = (const float*)d_in[4];
    float* out = (float*)d_out;

    __half *xh, *qkvh, *atth, *wqh, *wph;
    cudaGetSymbolAddress((void**)&xh, g_xh);
    cudaGetSymbolAddress((void**)&qkvh, g_qkvh);
    cudaGetSymbolAddress((void**)&atth, g_atth);
    cudaGetSymbolAddress((void**)&wqh, g_wqh);
    cudaGetSymbolAddress((void**)&wph, g_wph);

    const int smem_gemm = 3 * 2 * 128 * ASTR * (int)sizeof(__half);  // 61440
    cudaFuncSetAttribute(gemm_mma_kernel<true>,
                         cudaFuncAttributeMaxDynamicSharedMemorySize, smem_gemm);
    cudaFuncSetAttribute(gemm_mma_kernel<false>,
                         cudaFuncAttributeMaxDynamicSharedMemorySize, smem_gemm);
    const int smem_attn = 128 * QSTR * 2 + 3 * KVSTG;  // 73728
    cudaFuncSetAttribute(attn_mma_kernel,
                         cudaFuncAttributeMaxDynamicSharedMemorySize, smem_attn);

    // 1) x -> fp16
    convh_kernel<<<4096, 256>>>(x, xh);
    // 2) w_qkv -> transposed fp16 [3072,1024]
    tconvh_kernel<<<dim3(96, 32), 256>>>(w_qkv, wqh, 3072);
    // 3) QKV GEMM (fp16 out, bias fused)
    gemm_mma_kernel<true><<<dim3(24, 32), 256, smem_gemm>>>(
        xh, wqh, b_qkv, nullptr, qkvh, 4096, 3072);
    // 4) causal flash attention (fp16 in/out)
    attn_mma_kernel<<<dim3(2 * NH, T_SEQ / 128), 256, smem_attn>>>(qkvh, atth);
    // 5) w_proj -> transposed fp16 [1024,1024]
    tconvh_kernel<<<dim3(32, 32), 256>>>(w_proj, wph, 1024);
    // 6) proj GEMM (fp32 out, bias fused)
    gemm_mma_kernel<false><<<dim3(8, 32), 256, smem_gemm>>>(
        atth, wph, b_proj, out, nullptr, 4096, 1024);
}